// round 16
// baseline (speedup 1.0000x reference)
#include <cuda_runtime.h>
#include <cuda_fp16.h>
#include <math.h>

// ---------------- shapes ----------------
#define NB   32
#define NN   2048
#define CIN  128
#define COUT 256
#define CTXD 259
#define MTOT (NB * NN)

// ---------------- device scratch ----------------
__device__ float d_gate[NB * COUT];
__device__ float d_hbias[NB * COUT];
__device__ float d_G0[CIN * COUT];           // W^T Wtc^T (fp32)
__device__ float d_WtcT[COUT * COUT];        // W_tc^T fp32 (for bc)
__device__ float d_biasv[NB * 512];          // [b_layer | bc]
__device__ __half d_xh[MTOT * CIN];          // x fp16 [m][k]
__device__ __half d_B0h[CIN * COUT];         // WT hi [i][o]
__device__ __half d_WTl[CIN * COUT];         // WT lo
__device__ __half d_Wtch[COUT * COUT];       // WtcT hi [o][e]
__device__ __half d_Wtcl[COUT * COUT];       // WtcT lo
__device__ __half d_Ah[NB * COUT * COUT];    // A hi [o][e] per batch
__device__ __half d_Al[NB * COUT * COUT];    // A lo
__device__ __half d_Eth[NB * CIN * COUT];    // Et hi [i][e] per batch
__device__ __half d_Etl[NB * CIN * COUT];    // Et lo
__device__ __half d_B1h[NB * CIN * COUT];    // D fp16 per batch [i][e']
__device__ float d_T[MTOT * 256];            // t (compact, stride 256)
__device__ float d_ps[2 * NB * NN];          // BN sums per (nh, b, n)
__device__ float d_pq[2 * NB * NN];          // BN sumsq
__device__ float d_mean[NN];
__device__ float d_rstd[NN];

// ---------------- cp.async helpers ----------------
__device__ __forceinline__ void cpa16(unsigned sa, const void* g) {
    asm volatile("cp.async.cg.shared.global [%0], [%1], 16;" :: "r"(sa), "l"(g));
}
__device__ __forceinline__ void cp_commit() { asm volatile("cp.async.commit_group;"); }
__device__ __forceinline__ void cp_wait1()  { asm volatile("cp.async.wait_group 1;"); }
__device__ __forceinline__ void cp_wait0()  { asm volatile("cp.async.wait_group 0;"); }

// ---------------- mma helpers ----------------
__device__ __forceinline__ void ldsm4(unsigned& r0, unsigned& r1, unsigned& r2, unsigned& r3, unsigned addr) {
    asm volatile("ldmatrix.sync.aligned.m8n8.x4.shared.b16 {%0,%1,%2,%3}, [%4];"
                 : "=r"(r0), "=r"(r1), "=r"(r2), "=r"(r3) : "r"(addr));
}
__device__ __forceinline__ void ldsm4t(unsigned& r0, unsigned& r1, unsigned& r2, unsigned& r3, unsigned addr) {
    asm volatile("ldmatrix.sync.aligned.m8n8.x4.trans.shared.b16 {%0,%1,%2,%3}, [%4];"
                 : "=r"(r0), "=r"(r1), "=r"(r2), "=r"(r3) : "r"(addr));
}
__device__ __forceinline__ void mma16816(float* c, const unsigned* a, unsigned b0, unsigned b1) {
    asm volatile("mma.sync.aligned.m16n8k16.row.col.f32.f16.f16.f32 "
                 "{%0,%1,%2,%3}, {%4,%5,%6,%7}, {%8,%9}, {%0,%1,%2,%3};"
                 : "+f"(c[0]), "+f"(c[1]), "+f"(c[2]), "+f"(c[3])
                 : "r"(a[0]), "r"(a[1]), "r"(a[2]), "r"(a[3]), "r"(b0), "r"(b1));
}

// ================= half-GEMM: 128 rows x 128 cols per CTA, K=128 fp16, one-shot smem =================
// grid (512, 2): mt = blockIdx.x, nh = blockIdx.y (column half).
// MODE 0 (T): B = D[b]; epilogue adds t-bias, writes d_T + BN partials.
// MODE 1 (X): B = WT;   epilogue computes x1 and the FULL final expression -> out.
#define GSA 136                      // A smem row stride (halves)
#define GSB 136                      // B smem row stride (halves)
#define GOFFB (128 * GSA)            // 17408 halves
#define SMEM_G_BYTES ((128 * GSA + 128 * GSB) * 2)   // 69632 B

template<int MODE>
__global__ __launch_bounds__(256, 3) void k_gemm_half(
    const float* __restrict__ b_layer, const float* __restrict__ gamma,
    const float* __restrict__ beta, float* __restrict__ out)
{
    extern __shared__ __half sm[];
    __shared__ float2 sred[2][128];
    const int tid = threadIdx.x;
    const int wid = tid >> 5, lane = tid & 31;
    const int warp_m = (wid >> 1) * 32;
    const int warp_n = (wid & 1) * 64;
    const int mt = blockIdx.x;             // 0..511
    const int nh = blockIdx.y;             // 0..1
    const int b  = mt >> 4;
    const int m0 = mt * 128;
    const unsigned sbase = (unsigned)__cvta_generic_to_shared(sm);

    const __half* srcB = ((MODE == 0) ? d_B1h + (size_t)b * (CIN * COUT) : d_B0h) + nh * 128;

    // one-shot load: A (x tile 128x128) + B half (128x128)
    #pragma unroll
    for (int j = 0; j < 8; j++) {
        int idx = j * 256 + tid;
        int r = idx >> 4, c8 = (idx & 15) << 3;
        cpa16(sbase + (r * GSA + c8) * 2, d_xh + (size_t)(m0 + r) * CIN + c8);
        cpa16(sbase + (GOFFB + r * GSB + c8) * 2, srcB + (size_t)r * COUT + c8);
    }
    cp_commit();

    float acc[2][8][4];
    #pragma unroll
    for (int t = 0; t < 2; t++)
        #pragma unroll
        for (int f = 0; f < 8; f++)
            #pragma unroll
            for (int r = 0; r < 4; r++) acc[t][f][r] = 0.f;

    cp_wait0();
    __syncthreads();

    const int arow = lane & 15;
    const int asub = (lane >> 4) << 3;

    #pragma unroll
    for (int ks = 0; ks < 8; ks++) {
        unsigned ah[2][4], bh[4][4];
        #pragma unroll
        for (int t = 0; t < 2; t++) {
            int mrow = warp_m + t * 16 + arow;
            ldsm4(ah[t][0], ah[t][1], ah[t][2], ah[t][3],
                  sbase + (mrow * GSA + ks * 16 + asub) * 2);
        }
        #pragma unroll
        for (int nb = 0; nb < 4; nb++) {
            int ncol = warp_n + nb * 16 + asub;
            ldsm4t(bh[nb][0], bh[nb][1], bh[nb][2], bh[nb][3],
                   sbase + (GOFFB + (ks * 16 + arow) * GSB + ncol) * 2);
        }
        #pragma unroll
        for (int t = 0; t < 2; t++)
            #pragma unroll
            for (int nb = 0; nb < 4; nb++)
                #pragma unroll
                for (int j = 0; j < 2; j++)
                    mma16816(acc[t][nb * 2 + j], ah[t], bh[nb][2 * j], bh[nb][2 * j + 1]);
    }

    // ---- epilogue ----
    float sr[2][2] = {{0.f, 0.f}, {0.f, 0.f}};
    float qr[2][2] = {{0.f, 0.f}, {0.f, 0.f}};
    #pragma unroll
    for (int t = 0; t < 2; t++) {
        size_t row = (size_t)m0 + warp_m + t * 16 + (lane >> 2);
        if (MODE == 0) {
            #pragma unroll
            for (int nb = 0; nb < 4; nb++)
                #pragma unroll
                for (int j = 0; j < 2; j++) {
                    int col = nh * 128 + warp_n + nb * 16 + j * 8 + ((lane & 3) << 1);
                    float2 bv = *(const float2*)(d_biasv + b * 512 + 256 + col);
                    const float* a = acc[t][nb * 2 + j];
                    float y0 = a[0] + bv.x, y1 = a[1] + bv.y;
                    float y2 = a[2] + bv.x, y3 = a[3] + bv.y;
                    *(float2*)(d_T + row * 256 + col) = make_float2(y0, y1);
                    *(float2*)(d_T + (row + 8) * 256 + col) = make_float2(y2, y3);
                    sr[t][0] += y0 + y1; qr[t][0] += y0 * y0 + y1 * y1;
                    sr[t][1] += y2 + y3; qr[t][1] += y2 * y2 + y3 * y3;
                }
        } else {
            int nloc = (mt & 15) * 128 + warp_m + t * 16 + (lane >> 2);
            float mr0 = d_mean[nloc],     rs0 = d_rstd[nloc];
            float gm0 = gamma[nloc],      bt0 = beta[nloc];
            float mr1 = d_mean[nloc + 8], rs1 = d_rstd[nloc + 8];
            float gm1 = gamma[nloc + 8],  bt1 = beta[nloc + 8];
            #pragma unroll
            for (int nb = 0; nb < 4; nb++)
                #pragma unroll
                for (int j = 0; j < 2; j++) {
                    int col = nh * 128 + warp_n + nb * 16 + j * 8 + ((lane & 3) << 1);
                    float2 bl = *(const float2*)(b_layer + col);
                    float2 gt = *(const float2*)(d_gate + b * 256 + col);
                    float2 hb = *(const float2*)(d_hbias + b * 256 + col);
                    const float* a = acc[t][nb * 2 + j];
                    {
                        float2 tv = *(const float2*)(d_T + row * 256 + col);
                        float bn0 = fmaxf(fmaf((tv.x - mr0) * rs0, gm0, bt0), 0.f);
                        float bn1 = fmaxf(fmaf((tv.y - mr0) * rs0, gm0, bt0), 0.f);
                        float o0 = fmaf(a[0] + bl.x + bn0, gt.x, hb.x);
                        float o1 = fmaf(a[1] + bl.y + bn1, gt.y, hb.y);
                        *(float2*)(out + row * 256 + col) = make_float2(o0, o1);
                    }
                    {
                        float2 tv = *(const float2*)(d_T + (row + 8) * 256 + col);
                        float bn0 = fmaxf(fmaf((tv.x - mr1) * rs1, gm1, bt1), 0.f);
                        float bn1 = fmaxf(fmaf((tv.y - mr1) * rs1, gm1, bt1), 0.f);
                        float o0 = fmaf(a[2] + bl.x + bn0, gt.x, hb.x);
                        float o1 = fmaf(a[3] + bl.y + bn1, gt.y, hb.y);
                        *(float2*)(out + (row + 8) * 256 + col) = make_float2(o0, o1);
                    }
                }
        }
    }

    if (MODE == 0) {
        // per-row partial BN sums over this CTA's 128 columns
        #pragma unroll
        for (int t = 0; t < 2; t++)
            #pragma unroll
            for (int rr = 0; rr < 2; rr++) {
                float s = sr[t][rr], q = qr[t][rr];
                s += __shfl_xor_sync(0xffffffffu, s, 1);
                q += __shfl_xor_sync(0xffffffffu, q, 1);
                s += __shfl_xor_sync(0xffffffffu, s, 2);
                q += __shfl_xor_sync(0xffffffffu, q, 2);
                if ((lane & 3) == 0) {
                    int r = warp_m + t * 16 + rr * 8 + (lane >> 2);
                    sred[wid & 1][r] = make_float2(s, q);
                }
            }
        __syncthreads();
        if (tid < 128) {
            float2 u = sred[0][tid], w = sred[1][tid];
            int n = (mt & 15) * 128 + tid;
            size_t o = ((size_t)nh * NB + b) * NN + n;
            d_ps[o] = u.x + w.x;
            d_pq[o] = u.y + w.y;
        }
    }
}

// ================= small tensor GEMM: 128x128 tile, K=256, 3-MMA hi/lo split =================
#define SA 136
#define TSA 40
#define TS_AH 0
#define TS_AL (128 * TSA)
#define TS_BH (2 * 128 * TSA)
#define TS_BL (TS_BH + 32 * SA)
#define TS_PER (TS_BL + 32 * SA)
#define SMEM_TS_BYTES (2 * TS_PER * 2)

template<int MODE>
__device__ __forceinline__ void tcg128(
    const __half* __restrict__ Agh, const __half* __restrict__ Agl, int lda,
    const __half* __restrict__ Bgh, const __half* __restrict__ Bgl, int ldb,
    float* __restrict__ Cf, const float* __restrict__ G,
    __half* __restrict__ Ch, __half* __restrict__ Cl, int ldc)
{
    extern __shared__ __half sm[];
    const int tid = threadIdx.x;
    const int wid = tid >> 5, lane = tid & 31;
    const int warp_m = (wid >> 1) * 32;
    const int warp_n = (wid & 1) * 64;
    const unsigned sbase = (unsigned)__cvta_generic_to_shared(sm);

    auto fill = [&](int buf, int k0) {
        unsigned base = sbase + buf * (TS_PER * 2);
        #pragma unroll
        for (int j = 0; j < 2; j++) {
            int idx = j * 256 + tid;
            int r = idx >> 2, c8 = (idx & 3) << 3;
            cpa16(base + (TS_AH + r * TSA + c8) * 2, Agh + (size_t)r * lda + k0 + c8);
            cpa16(base + (TS_AL + r * TSA + c8) * 2, Agl + (size_t)r * lda + k0 + c8);
            int br = idx >> 4, bc8 = (idx & 15) << 3;
            cpa16(base + (TS_BH + br * SA + bc8) * 2, Bgh + (size_t)(k0 + br) * ldb + bc8);
            cpa16(base + (TS_BL + br * SA + bc8) * 2, Bgl + (size_t)(k0 + br) * ldb + bc8);
        }
    };

    float acc[2][8][4];
    #pragma unroll
    for (int t = 0; t < 2; t++)
        #pragma unroll
        for (int f = 0; f < 8; f++)
            #pragma unroll
            for (int r = 0; r < 4; r++) acc[t][f][r] = 0.f;

    fill(0, 0);
    cp_commit();

    const int arow = lane & 15;
    const int asub = (lane >> 4) << 3;

    #pragma unroll
    for (int c = 0; c < 8; c++) {
        int cur = c & 1;
        if (c < 7) { fill(cur ^ 1, (c + 1) * 32); cp_commit(); cp_wait1(); }
        else cp_wait0();
        __syncthreads();

        unsigned base = sbase + cur * (TS_PER * 2);
        #pragma unroll
        for (int ks = 0; ks < 2; ks++) {
            unsigned ah[2][4], al[2][4], bh[4][4], bl[4][4];
            #pragma unroll
            for (int t = 0; t < 2; t++) {
                int mrow = warp_m + t * 16 + arow;
                int acol = ks * 16 + asub;
                ldsm4(ah[t][0], ah[t][1], ah[t][2], ah[t][3],
                      base + (TS_AH + mrow * TSA + acol) * 2);
                ldsm4(al[t][0], al[t][1], al[t][2], al[t][3],
                      base + (TS_AL + mrow * TSA + acol) * 2);
            }
            #pragma unroll
            for (int nb = 0; nb < 4; nb++) {
                int krow = ks * 16 + arow;
                int ncol = warp_n + nb * 16 + asub;
                ldsm4t(bh[nb][0], bh[nb][1], bh[nb][2], bh[nb][3],
                       base + (TS_BH + krow * SA + ncol) * 2);
                ldsm4t(bl[nb][0], bl[nb][1], bl[nb][2], bl[nb][3],
                       base + (TS_BL + krow * SA + ncol) * 2);
            }
            #pragma unroll
            for (int t = 0; t < 2; t++)
                #pragma unroll
                for (int nb = 0; nb < 4; nb++)
                    #pragma unroll
                    for (int j = 0; j < 2; j++) {
                        float* cc = acc[t][nb * 2 + j];
                        mma16816(cc, ah[t], bh[nb][2 * j], bh[nb][2 * j + 1]);
                        mma16816(cc, al[t], bh[nb][2 * j], bh[nb][2 * j + 1]);
                        mma16816(cc, ah[t], bl[nb][2 * j], bl[nb][2 * j + 1]);
                    }
        }
        __syncthreads();
    }

    #pragma unroll
    for (int t = 0; t < 2; t++) {
        int row = warp_m + t * 16 + (lane >> 2);
        #pragma unroll
        for (int nb = 0; nb < 4; nb++)
            #pragma unroll
            for (int j = 0; j < 2; j++) {
                int col = warp_n + nb * 16 + j * 8 + ((lane & 3) << 1);
                const float* a = acc[t][nb * 2 + j];
                #pragma unroll
                for (int rr = 0; rr < 2; rr++) {
                    int r = row + rr * 8;
                    float v0 = a[2 * rr], v1 = a[2 * rr + 1];
                    if (MODE == 0) {
                        *(float2*)(Cf + (size_t)r * ldc + col) = make_float2(v0, v1);
                    } else if (MODE == 1) {
                        __half h0 = __float2half_rn(v0), h1 = __float2half_rn(v1);
                        union { __half h[2]; unsigned u; } ph, pl;
                        ph.h[0] = h0; ph.h[1] = h1;
                        pl.h[0] = __float2half_rn(v0 - __half2float(h0));
                        pl.h[1] = __float2half_rn(v1 - __half2float(h1));
                        *(unsigned*)(Ch + (size_t)r * ldc + col) = ph.u;
                        *(unsigned*)(Cl + (size_t)r * ldc + col) = pl.u;
                    } else {
                        float2 g = *(const float2*)(G + (size_t)r * ldc + col);
                        union { __half h[2]; unsigned u; } ph;
                        ph.h[0] = __float2half_rn(g.x - v0);
                        ph.h[1] = __float2half_rn(g.y - v1);
                        *(unsigned*)(Ch + (size_t)r * ldc + col) = ph.u;
                    }
                }
            }
    }
}

__global__ __launch_bounds__(256) void k_gemm_Et() {
    int z = blockIdx.z, nt = blockIdx.x;
    if (z == NB) {
        tcg128<0>(d_B0h, d_WTl, COUT, d_Wtch + nt * 128, d_Wtcl + nt * 128, COUT,
                  d_G0 + nt * 128, nullptr, nullptr, nullptr, COUT);
    } else {
        const __half* Bh = d_Ah + (size_t)z * (COUT * COUT) + nt * 128;
        const __half* Bl = d_Al + (size_t)z * (COUT * COUT) + nt * 128;
        tcg128<1>(d_B0h, d_WTl, COUT, Bh, Bl, COUT,
                  nullptr, nullptr,
                  d_Eth + (size_t)z * (CIN * COUT) + nt * 128,
                  d_Etl + (size_t)z * (CIN * COUT) + nt * 128, COUT);
    }
}

__global__ __launch_bounds__(256) void k_gemm_D2() {
    int b = blockIdx.z, nt = blockIdx.x;
    tcg128<2>(d_Eth + (size_t)b * (CIN * COUT), d_Etl + (size_t)b * (CIN * COUT), COUT,
              d_Wtch + nt * 128, d_Wtcl + nt * 128, COUT,
              nullptr, d_G0 + nt * 128,
              d_B1h + (size_t)b * (CIN * COUT) + nt * 128, nullptr, COUT);
}

// ================= x -> fp16 =================
__global__ void k_convx(const float* __restrict__ x) {
    size_t g = (size_t)blockIdx.x * 256 + threadIdx.x;
    float4 v = *(const float4*)(x + g * 4);
    half2 p0 = __floats2half2_rn(v.x, v.y);
    half2 p1 = __floats2half2_rn(v.z, v.w);
    union { half2 h[2]; uint2 u; } cv;
    cv.h[0] = p0; cv.h[1] = p1;
    *(uint2*)(d_xh + g * 4) = cv.u;
}

// ---------------- transpose + fp16 weight images ----------------
__global__ void k_transpose(const float* __restrict__ Wl, const float* __restrict__ Wtc) {
    int tid = blockIdx.x * 256 + threadIdx.x;
    if (blockIdx.y == 0) {
        if (tid < CIN * COUT) {
            int i = tid >> 8, o = tid & 255;
            float v = Wl[o * CIN + i];
            __half h = __float2half_rn(v);
            d_B0h[tid] = h;
            d_WTl[tid] = __float2half_rn(v - __half2float(h));
        }
    } else {
        if (tid < COUT * COUT) {
            int o = tid >> 8, e = tid & 255;
            float v = Wtc[e * COUT + o];
            d_WtcT[tid] = v;
            __half h = __float2half_rn(v);
            d_Wtch[tid] = h;
            d_Wtcl[tid] = __float2half_rn(v - __half2float(h));
        }
    }
}

// ---------------- per-batch stage 1 ----------------
__global__ __launch_bounds__(256) void k_s1(
    const float* __restrict__ ctx, const float* __restrict__ Wg,
    const float* __restrict__ bg,  const float* __restrict__ Whb,
    const float* __restrict__ Wk,  const float* __restrict__ Wv)
{
    int b = blockIdx.x;
    int tid = threadIdx.x;
    __shared__ float cs[CTXD];
    __shared__ float ks[COUT], vs[COUT], ms[COUT], invr[COUT];
    __shared__ float vmm[2];

    for (int i = tid; i < CTXD; i += 256) cs[i] = ctx[b * CTXD + i];
    __syncthreads();

    int warp = tid >> 5, lane = tid & 31;
    for (int o = warp; o < COUT; o += 8) {
        float kk = 0.f, vv = 0.f, gg = 0.f, hb = 0.f;
        for (int c = lane; c < 256; c += 32) {
            float cv = cs[c];
            kk = fmaf(cv, Wk[o * 256 + c], kk);
            vv = fmaf(cv, Wv[o * 256 + c], vv);
        }
        for (int c = lane; c < CTXD; c += 32) {
            float cv = cs[c];
            gg = fmaf(cv, Wg[o * CTXD + c], gg);
            hb = fmaf(cv, Whb[o * CTXD + c], hb);
        }
        #pragma unroll
        for (int s = 16; s; s >>= 1) {
            kk += __shfl_xor_sync(0xffffffffu, kk, s);
            vv += __shfl_xor_sync(0xffffffffu, vv, s);
            gg += __shfl_xor_sync(0xffffffffu, gg, s);
            hb += __shfl_xor_sync(0xffffffffu, hb, s);
        }
        if (lane == 0) {
            ks[o] = kk; vs[o] = vv;
            float z = gg + bg[o];
            d_gate[b * COUT + o]  = 1.f / (1.f + expf(-z));
            d_hbias[b * COUT + o] = hb;
        }
    }
    __syncthreads();

    if (tid == 0) {
        float mx = vs[0], mn = vs[0];
        for (int i = 1; i < COUT; i++) { mx = fmaxf(mx, vs[i]); mn = fminf(mn, vs[i]); }
        vmm[0] = mx; vmm[1] = mn;
    }
    __syncthreads();

    {
        float kk = ks[tid];
        float m = (kk >= 0.f) ? kk * vmm[0] : kk * vmm[1];
        float r = 0.f;
        for (int e = 0; e < COUT; e++) r += expf(fmaf(kk, vs[e], -m));
        ms[tid] = m;
        invr[tid] = 1.f / r;
    }
    __syncthreads();

    float ve = vs[tid];
    float csum = 0.f;
    for (int o = 0; o < COUT; o++)
        csum += expf(fmaf(ks[o], ve, -ms[o])) * invr[o];
    float cinv = 1.f / (1e-9f + csum);

    __half* Ahb = d_Ah + (size_t)b * (COUT * COUT);
    __half* Alb = d_Al + (size_t)b * (COUT * COUT);
    for (int o = 0; o < COUT; o++) {
        float a = expf(fmaf(ks[o], ve, -ms[o])) * invr[o] * cinv;
        __half h = __float2half_rn(a);
        Ahb[o * COUT + tid] = h;
        Alb[o * COUT + tid] = __float2half_rn(a - __half2float(h));
    }
}

// biasv: [b_layer | b_tc + (b_layer^T (I-A)) Wtc^T]
__global__ void k_bc(const float* __restrict__ b_layer, const float* __restrict__ b_tc) {
    int b = blockIdx.x, e = threadIdx.x;
    __shared__ float v[COUT];
    const __half* Ahb = d_Ah + (size_t)b * (COUT * COUT);
    const __half* Alb = d_Al + (size_t)b * (COUT * COUT);
    float s = 0.f;
    for (int o = 0; o < COUT; o++) {
        float a = __half2float(Ahb[o * COUT + e]) + __half2float(Alb[o * COUT + e]);
        s = fmaf(b_layer[o], a, s);
    }
    v[e] = b_layer[e] - s;
    __syncthreads();
    float s2 = b_tc[e];
    for (int k = 0; k < COUT; k++) s2 = fmaf(v[k], d_WtcT[k * COUT + e], s2);
    d_biasv[b * 512 + e] = b_layer[e];
    d_biasv[b * 512 + 256 + e] = s2;
}

// ---------------- BN stats ----------------
__global__ void k_bnstats2() {
    int n = blockIdx.x * 256 + threadIdx.x;
    float s = 0.f, q = 0.f;
    #pragma unroll
    for (int t = 0; t < 2 * NB; t++) {
        s += d_ps[(size_t)t * NN + n];
        q += d_pq[(size_t)t * NN + n];
    }
    float mean = s * (1.f / 8192.f);
    float var  = q * (1.f / 8192.f) - mean * mean;
    d_mean[n] = mean;
    d_rstd[n] = rsqrtf(var + 1e-5f);
}

// ---------------- launch ----------------
extern "C" void kernel_launch(void* const* d_in, const int* in_sizes, int n_in,
                              void* d_out, int out_size)
{
    (void)in_sizes; (void)n_in; (void)out_size;
    const float* ctx     = (const float*)d_in[0];
    const float* x       = (const float*)d_in[1];
    const float* W_layer = (const float*)d_in[2];
    const float* b_layer = (const float*)d_in[3];
    const float* W_hbias = (const float*)d_in[4];
    const float* W_gate  = (const float*)d_in[5];
    const float* b_gate  = (const float*)d_in[6];
    const float* W_k     = (const float*)d_in[7];
    const float* W_v     = (const float*)d_in[8];
    const float* W_tc    = (const float*)d_in[9];
    const float* b_tc    = (const float*)d_in[10];
    const float* gamma   = (const float*)d_in[11];
    const float* beta    = (const float*)d_in[12];
    float* out = (float*)d_out;

    static int smem_set = 0;
    if (!smem_set) {
        cudaFuncSetAttribute(k_gemm_half<0>,
                             cudaFuncAttributeMaxDynamicSharedMemorySize, SMEM_G_BYTES);
        cudaFuncSetAttribute(k_gemm_half<1>,
                             cudaFuncAttributeMaxDynamicSharedMemorySize, SMEM_G_BYTES);
        cudaFuncSetAttribute(k_gemm_Et,
                             cudaFuncAttributeMaxDynamicSharedMemorySize, SMEM_TS_BYTES);
        cudaFuncSetAttribute(k_gemm_D2,
                             cudaFuncAttributeMaxDynamicSharedMemorySize, SMEM_TS_BYTES);
        smem_set = 1;
    }

    k_transpose<<<dim3(256, 2), 256>>>(W_layer, W_tc);
    k_convx<<<(MTOT * CIN) / 1024, 256>>>(x);
    k_s1<<<NB, 256>>>(ctx, W_gate, b_gate, W_hbias, W_k, W_v);
    k_gemm_Et<<<dim3(2, 1, NB + 1), 256, SMEM_TS_BYTES>>>();
    k_gemm_D2<<<dim3(2, 1, NB), 256, SMEM_TS_BYTES>>>();
    k_bc<<<NB, 256>>>(b_layer, b_tc);
    k_gemm_half<0><<<dim3(512, 2), 256, SMEM_G_BYTES>>>(b_layer, gamma, beta, out);
    k_bnstats2<<<NN / 256, 256>>>();
    k_gemm_half<1><<<dim3(512, 2), 256, SMEM_G_BYTES>>>(b_layer, gamma, beta, out);
}

// round 17
// speedup vs baseline: 1.2034x; 1.2034x over previous
#include <cuda_runtime.h>
#include <cuda_fp16.h>
#include <math.h>

// ---------------- shapes ----------------
#define NB   32
#define NN   2048
#define CIN  128
#define COUT 256
#define CTXD 259
#define MTOT (NB * NN)

// ---------------- device scratch ----------------
__device__ float d_gate[NB * COUT];
__device__ float d_hbias[NB * COUT];
__device__ float d_G0[CIN * COUT];           // W^T Wtc^T (fp32)
__device__ float d_WtcT[COUT * COUT];        // W_tc^T fp32 (for bc)
__device__ float d_biasv[NB * 512];          // [b_layer | bc]
__device__ __half d_xh[MTOT * CIN];          // x fp16 [m][k]
__device__ __half d_B0h[CIN * COUT];         // WT hi [i][o]
__device__ __half d_WTl[CIN * COUT];         // WT lo
__device__ __half d_Wtch[COUT * COUT];       // WtcT hi [o][e]
__device__ __half d_Wtcl[COUT * COUT];       // WtcT lo
__device__ __half d_Ah[NB * COUT * COUT];    // A hi [o][e] per batch
__device__ __half d_Al[NB * COUT * COUT];    // A lo
__device__ __half d_Eth[NB * CIN * COUT];    // Et hi [i][e] per batch
__device__ __half d_Etl[NB * CIN * COUT];    // Et lo
__device__ __half d_B1h[NB * CIN * COUT];    // D fp16 per batch [i][e']
__device__ float d_T[MTOT * 256];            // t (compact, stride 256)
__device__ float d_ps[NB * NN];              // BN sums per (b, n)
__device__ float d_pq[NB * NN];              // BN sumsq per (b, n)
__device__ float d_mean[NN];
__device__ float d_rstd[NN];

// ---------------- cp.async helpers ----------------
__device__ __forceinline__ void cpa16(unsigned sa, const void* g) {
    asm volatile("cp.async.cg.shared.global [%0], [%1], 16;" :: "r"(sa), "l"(g));
}
__device__ __forceinline__ void cp_commit() { asm volatile("cp.async.commit_group;"); }
__device__ __forceinline__ void cp_wait1()  { asm volatile("cp.async.wait_group 1;"); }
__device__ __forceinline__ void cp_wait0()  { asm volatile("cp.async.wait_group 0;"); }
__device__ __forceinline__ void cp_wait_c(int c) {
    // wait so that chunk c is complete when 4 groups were committed (unrolled callers pass literals)
    if (c == 0)      asm volatile("cp.async.wait_group 3;");
    else if (c == 1) asm volatile("cp.async.wait_group 2;");
    else if (c == 2) asm volatile("cp.async.wait_group 1;");
    else             asm volatile("cp.async.wait_group 0;");
}

// ---------------- mma helpers ----------------
__device__ __forceinline__ void ldsm4(unsigned& r0, unsigned& r1, unsigned& r2, unsigned& r3, unsigned addr) {
    asm volatile("ldmatrix.sync.aligned.m8n8.x4.shared.b16 {%0,%1,%2,%3}, [%4];"
                 : "=r"(r0), "=r"(r1), "=r"(r2), "=r"(r3) : "r"(addr));
}
__device__ __forceinline__ void ldsm4t(unsigned& r0, unsigned& r1, unsigned& r2, unsigned& r3, unsigned addr) {
    asm volatile("ldmatrix.sync.aligned.m8n8.x4.trans.shared.b16 {%0,%1,%2,%3}, [%4];"
                 : "=r"(r0), "=r"(r1), "=r"(r2), "=r"(r3) : "r"(addr));
}
__device__ __forceinline__ void mma16816(float* c, const unsigned* a, unsigned b0, unsigned b1) {
    asm volatile("mma.sync.aligned.m16n8k16.row.col.f32.f16.f16.f32 "
                 "{%0,%1,%2,%3}, {%4,%5,%6,%7}, {%8,%9}, {%0,%1,%2,%3};"
                 : "+f"(c[0]), "+f"(c[1]), "+f"(c[2]), "+f"(c[3])
                 : "r"(a[0]), "r"(a[1]), "r"(a[2]), "r"(a[3]), "r"(b0), "r"(b1));
}

// ================= half-GEMM: 128 rows x 256 cols, K=128 fp16, staged smem =================
// grid 512. MODE 0 (T): B = D[b]; writes d_T + BN row sums.
//           MODE 1 (X): B = WT; computes x1 + FULL final expression -> out.
// Load is split into 4 K-chunk commit groups so nh=0 compute overlaps the tail of the load.
#define GSA 136                      // A smem row stride (halves)
#define GOFFB 17408                  // B offset (halves) = 128*136
#define GSB 264                      // B smem row stride (halves)
#define SMEM_G_BYTES 102400          // (128*136 + 128*264) * 2

template<int MODE>
__global__ __launch_bounds__(256, 2) void k_gemm_half(
    const float* __restrict__ b_layer, const float* __restrict__ gamma,
    const float* __restrict__ beta, float* __restrict__ out)
{
    extern __shared__ __half sm[];
    __shared__ float2 sred[2][128];
    const int tid = threadIdx.x;
    const int wid = tid >> 5, lane = tid & 31;
    const int warp_m = (wid >> 1) * 32;
    const int warp_n = (wid & 1) * 64;
    const int mt = blockIdx.x;             // 0..511
    const int b  = mt >> 4;
    const int m0 = mt * 128;
    const unsigned sbase = (unsigned)__cvta_generic_to_shared(sm);

    const __half* srcB = (MODE == 0) ? d_B1h + (size_t)b * (CIN * COUT) : d_B0h;

    // staged load: 4 commit groups, each = A k-cols [32c,32c+32) + B k-rows [32c,32c+32)
    #pragma unroll
    for (int c = 0; c < 4; c++) {
        int k0 = c * 32;
        #pragma unroll
        for (int j = 0; j < 2; j++) {            // A: 512 transfers/chunk
            int t = j * 256 + tid;
            int r = t >> 2, kc = (t & 3) << 3;
            cpa16(sbase + (r * GSA + k0 + kc) * 2,
                  d_xh + (size_t)(m0 + r) * CIN + k0 + kc);
        }
        #pragma unroll
        for (int j = 0; j < 4; j++) {            // B: 1024 transfers/chunk
            int t = j * 256 + tid;
            int r = t >> 5, c8 = (t & 31) << 3;
            cpa16(sbase + (GOFFB + (k0 + r) * GSB + c8) * 2,
                  srcB + (size_t)(k0 + r) * COUT + c8);
        }
        cp_commit();
    }

    const int arow = lane & 15;
    const int asub = (lane >> 4) << 3;

    float sr[2][2] = {{0.f, 0.f}, {0.f, 0.f}};
    float qr[2][2] = {{0.f, 0.f}, {0.f, 0.f}};

    #pragma unroll
    for (int nh = 0; nh < 2; nh++) {
        float acc[2][8][4];
        #pragma unroll
        for (int t = 0; t < 2; t++)
            #pragma unroll
            for (int f = 0; f < 8; f++)
                #pragma unroll
                for (int r = 0; r < 4; r++) acc[t][f][r] = 0.f;

        #pragma unroll
        for (int c = 0; c < 4; c++) {
            if (nh == 0) {                       // progressive arrival on first pass
                cp_wait_c(c);
                __syncthreads();
            }
            #pragma unroll
            for (int ks2 = 0; ks2 < 2; ks2++) {
                int ks = c * 2 + ks2;
                unsigned ah[2][4], bh[4][4];
                #pragma unroll
                for (int t = 0; t < 2; t++) {
                    int mrow = warp_m + t * 16 + arow;
                    ldsm4(ah[t][0], ah[t][1], ah[t][2], ah[t][3],
                          sbase + (mrow * GSA + ks * 16 + asub) * 2);
                }
                #pragma unroll
                for (int nb = 0; nb < 4; nb++) {
                    int ncol = nh * 128 + warp_n + nb * 16 + asub;
                    ldsm4t(bh[nb][0], bh[nb][1], bh[nb][2], bh[nb][3],
                           sbase + (GOFFB + (ks * 16 + arow) * GSB + ncol) * 2);
                }
                #pragma unroll
                for (int t = 0; t < 2; t++)
                    #pragma unroll
                    for (int nb = 0; nb < 4; nb++)
                        #pragma unroll
                        for (int j = 0; j < 2; j++)
                            mma16816(acc[t][nb * 2 + j], ah[t], bh[nb][2 * j], bh[nb][2 * j + 1]);
            }
        }

        // ---- epilogue for this n-half ----
        #pragma unroll
        for (int t = 0; t < 2; t++) {
            size_t row = (size_t)m0 + warp_m + t * 16 + (lane >> 2);
            if (MODE == 0) {
                #pragma unroll
                for (int nb = 0; nb < 4; nb++)
                    #pragma unroll
                    for (int j = 0; j < 2; j++) {
                        int col = nh * 128 + warp_n + nb * 16 + j * 8 + ((lane & 3) << 1);
                        float2 bv = *(const float2*)(d_biasv + b * 512 + 256 + col);
                        const float* a = acc[t][nb * 2 + j];
                        float y0 = a[0] + bv.x, y1 = a[1] + bv.y;
                        float y2 = a[2] + bv.x, y3 = a[3] + bv.y;
                        *(float2*)(d_T + row * 256 + col) = make_float2(y0, y1);
                        *(float2*)(d_T + (row + 8) * 256 + col) = make_float2(y2, y3);
                        sr[t][0] += y0 + y1; qr[t][0] += y0 * y0 + y1 * y1;
                        sr[t][1] += y2 + y3; qr[t][1] += y2 * y2 + y3 * y3;
                    }
            } else {
                int nloc = (mt & 15) * 128 + warp_m + t * 16 + (lane >> 2);
                float mr0 = d_mean[nloc],     rs0 = d_rstd[nloc];
                float gm0 = gamma[nloc],      bt0 = beta[nloc];
                float mr1 = d_mean[nloc + 8], rs1 = d_rstd[nloc + 8];
                float gm1 = gamma[nloc + 8],  bt1 = beta[nloc + 8];
                #pragma unroll
                for (int nb = 0; nb < 4; nb++)
                    #pragma unroll
                    for (int j = 0; j < 2; j++) {
                        int col = nh * 128 + warp_n + nb * 16 + j * 8 + ((lane & 3) << 1);
                        float2 bl = *(const float2*)(b_layer + col);
                        float2 gt = *(const float2*)(d_gate + b * 256 + col);
                        float2 hb = *(const float2*)(d_hbias + b * 256 + col);
                        const float* a = acc[t][nb * 2 + j];
                        {
                            float2 tv = *(const float2*)(d_T + row * 256 + col);
                            float bn0 = fmaxf(fmaf((tv.x - mr0) * rs0, gm0, bt0), 0.f);
                            float bn1 = fmaxf(fmaf((tv.y - mr0) * rs0, gm0, bt0), 0.f);
                            float o0 = fmaf(a[0] + bl.x + bn0, gt.x, hb.x);
                            float o1 = fmaf(a[1] + bl.y + bn1, gt.y, hb.y);
                            *(float2*)(out + row * 256 + col) = make_float2(o0, o1);
                        }
                        {
                            float2 tv = *(const float2*)(d_T + (row + 8) * 256 + col);
                            float bn0 = fmaxf(fmaf((tv.x - mr1) * rs1, gm1, bt1), 0.f);
                            float bn1 = fmaxf(fmaf((tv.y - mr1) * rs1, gm1, bt1), 0.f);
                            float o0 = fmaf(a[2] + bl.x + bn0, gt.x, hb.x);
                            float o1 = fmaf(a[3] + bl.y + bn1, gt.y, hb.y);
                            *(float2*)(out + (row + 8) * 256 + col) = make_float2(o0, o1);
                        }
                    }
            }
        }
    }

    if (MODE == 0) {
        // per-row BN sums: combine the two warp_n halves via smem, write d_ps/d_pq
        #pragma unroll
        for (int t = 0; t < 2; t++)
            #pragma unroll
            for (int rr = 0; rr < 2; rr++) {
                float s = sr[t][rr], q = qr[t][rr];
                s += __shfl_xor_sync(0xffffffffu, s, 1);
                q += __shfl_xor_sync(0xffffffffu, q, 1);
                s += __shfl_xor_sync(0xffffffffu, s, 2);
                q += __shfl_xor_sync(0xffffffffu, q, 2);
                if ((lane & 3) == 0) {
                    int r = warp_m + t * 16 + rr * 8 + (lane >> 2);
                    sred[wid & 1][r] = make_float2(s, q);
                }
            }
        __syncthreads();
        if (tid < 128) {
            float2 u = sred[0][tid], w = sred[1][tid];
            int n = (mt & 15) * 128 + tid;
            d_ps[(size_t)b * NN + n] = u.x + w.x;
            d_pq[(size_t)b * NN + n] = u.y + w.y;
        }
    }
}

// ================= small tensor GEMM: 128x128 tile, K=256, 3-MMA hi/lo split =================
#define SA 136
#define TSA 40
#define TS_AH 0
#define TS_AL (128 * TSA)
#define TS_BH (2 * 128 * TSA)
#define TS_BL (TS_BH + 32 * SA)
#define TS_PER (TS_BL + 32 * SA)
#define SMEM_TS_BYTES (2 * TS_PER * 2)

template<int MODE>
__device__ __forceinline__ void tcg128(
    const __half* __restrict__ Agh, const __half* __restrict__ Agl, int lda,
    const __half* __restrict__ Bgh, const __half* __restrict__ Bgl, int ldb,
    float* __restrict__ Cf, const float* __restrict__ G,
    __half* __restrict__ Ch, __half* __restrict__ Cl, int ldc)
{
    extern __shared__ __half sm[];
    const int tid = threadIdx.x;
    const int wid = tid >> 5, lane = tid & 31;
    const int warp_m = (wid >> 1) * 32;
    const int warp_n = (wid & 1) * 64;
    const unsigned sbase = (unsigned)__cvta_generic_to_shared(sm);

    auto fill = [&](int buf, int k0) {
        unsigned base = sbase + buf * (TS_PER * 2);
        #pragma unroll
        for (int j = 0; j < 2; j++) {
            int idx = j * 256 + tid;
            int r = idx >> 2, c8 = (idx & 3) << 3;
            cpa16(base + (TS_AH + r * TSA + c8) * 2, Agh + (size_t)r * lda + k0 + c8);
            cpa16(base + (TS_AL + r * TSA + c8) * 2, Agl + (size_t)r * lda + k0 + c8);
            int br = idx >> 4, bc8 = (idx & 15) << 3;
            cpa16(base + (TS_BH + br * SA + bc8) * 2, Bgh + (size_t)(k0 + br) * ldb + bc8);
            cpa16(base + (TS_BL + br * SA + bc8) * 2, Bgl + (size_t)(k0 + br) * ldb + bc8);
        }
    };

    float acc[2][8][4];
    #pragma unroll
    for (int t = 0; t < 2; t++)
        #pragma unroll
        for (int f = 0; f < 8; f++)
            #pragma unroll
            for (int r = 0; r < 4; r++) acc[t][f][r] = 0.f;

    fill(0, 0);
    cp_commit();

    const int arow = lane & 15;
    const int asub = (lane >> 4) << 3;

    #pragma unroll
    for (int c = 0; c < 8; c++) {
        int cur = c & 1;
        if (c < 7) { fill(cur ^ 1, (c + 1) * 32); cp_commit(); cp_wait1(); }
        else cp_wait0();
        __syncthreads();

        unsigned base = sbase + cur * (TS_PER * 2);
        #pragma unroll
        for (int ks = 0; ks < 2; ks++) {
            unsigned ah[2][4], al[2][4], bh[4][4], bl[4][4];
            #pragma unroll
            for (int t = 0; t < 2; t++) {
                int mrow = warp_m + t * 16 + arow;
                int acol = ks * 16 + asub;
                ldsm4(ah[t][0], ah[t][1], ah[t][2], ah[t][3],
                      base + (TS_AH + mrow * TSA + acol) * 2);
                ldsm4(al[t][0], al[t][1], al[t][2], al[t][3],
                      base + (TS_AL + mrow * TSA + acol) * 2);
            }
            #pragma unroll
            for (int nb = 0; nb < 4; nb++) {
                int krow = ks * 16 + arow;
                int ncol = warp_n + nb * 16 + asub;
                ldsm4t(bh[nb][0], bh[nb][1], bh[nb][2], bh[nb][3],
                       base + (TS_BH + krow * SA + ncol) * 2);
                ldsm4t(bl[nb][0], bl[nb][1], bl[nb][2], bl[nb][3],
                       base + (TS_BL + krow * SA + ncol) * 2);
            }
            #pragma unroll
            for (int t = 0; t < 2; t++)
                #pragma unroll
                for (int nb = 0; nb < 4; nb++)
                    #pragma unroll
                    for (int j = 0; j < 2; j++) {
                        float* cc = acc[t][nb * 2 + j];
                        mma16816(cc, ah[t], bh[nb][2 * j], bh[nb][2 * j + 1]);
                        mma16816(cc, al[t], bh[nb][2 * j], bh[nb][2 * j + 1]);
                        mma16816(cc, ah[t], bl[nb][2 * j], bl[nb][2 * j + 1]);
                    }
        }
        __syncthreads();
    }

    #pragma unroll
    for (int t = 0; t < 2; t++) {
        int row = warp_m + t * 16 + (lane >> 2);
        #pragma unroll
        for (int nb = 0; nb < 4; nb++)
            #pragma unroll
            for (int j = 0; j < 2; j++) {
                int col = warp_n + nb * 16 + j * 8 + ((lane & 3) << 1);
                const float* a = acc[t][nb * 2 + j];
                #pragma unroll
                for (int rr = 0; rr < 2; rr++) {
                    int r = row + rr * 8;
                    float v0 = a[2 * rr], v1 = a[2 * rr + 1];
                    if (MODE == 0) {
                        *(float2*)(Cf + (size_t)r * ldc + col) = make_float2(v0, v1);
                    } else if (MODE == 1) {
                        __half h0 = __float2half_rn(v0), h1 = __float2half_rn(v1);
                        union { __half h[2]; unsigned u; } ph, pl;
                        ph.h[0] = h0; ph.h[1] = h1;
                        pl.h[0] = __float2half_rn(v0 - __half2float(h0));
                        pl.h[1] = __float2half_rn(v1 - __half2float(h1));
                        *(unsigned*)(Ch + (size_t)r * ldc + col) = ph.u;
                        *(unsigned*)(Cl + (size_t)r * ldc + col) = pl.u;
                    } else {
                        float2 g = *(const float2*)(G + (size_t)r * ldc + col);
                        union { __half h[2]; unsigned u; } ph;
                        ph.h[0] = __float2half_rn(g.x - v0);
                        ph.h[1] = __float2half_rn(g.y - v1);
                        *(unsigned*)(Ch + (size_t)r * ldc + col) = ph.u;
                    }
                }
            }
    }
}

__global__ __launch_bounds__(256) void k_gemm_Et() {
    int z = blockIdx.z, nt = blockIdx.x;
    if (z == NB) {
        tcg128<0>(d_B0h, d_WTl, COUT, d_Wtch + nt * 128, d_Wtcl + nt * 128, COUT,
                  d_G0 + nt * 128, nullptr, nullptr, nullptr, COUT);
    } else {
        const __half* Bh = d_Ah + (size_t)z * (COUT * COUT) + nt * 128;
        const __half* Bl = d_Al + (size_t)z * (COUT * COUT) + nt * 128;
        tcg128<1>(d_B0h, d_WTl, COUT, Bh, Bl, COUT,
                  nullptr, nullptr,
                  d_Eth + (size_t)z * (CIN * COUT) + nt * 128,
                  d_Etl + (size_t)z * (CIN * COUT) + nt * 128, COUT);
    }
}

__global__ __launch_bounds__(256) void k_gemm_D2() {
    int b = blockIdx.z, nt = blockIdx.x;
    tcg128<2>(d_Eth + (size_t)b * (CIN * COUT), d_Etl + (size_t)b * (CIN * COUT), COUT,
              d_Wtch + nt * 128, d_Wtcl + nt * 128, COUT,
              nullptr, d_G0 + nt * 128,
              d_B1h + (size_t)b * (CIN * COUT) + nt * 128, nullptr, COUT);
}

// ================= x -> fp16 =================
__global__ void k_convx(const float* __restrict__ x) {
    size_t g = (size_t)blockIdx.x * 256 + threadIdx.x;
    float4 v = *(const float4*)(x + g * 4);
    half2 p0 = __floats2half2_rn(v.x, v.y);
    half2 p1 = __floats2half2_rn(v.z, v.w);
    union { half2 h[2]; uint2 u; } cv;
    cv.h[0] = p0; cv.h[1] = p1;
    *(uint2*)(d_xh + g * 4) = cv.u;
}

// ---------------- transpose + fp16 weight images ----------------
__global__ void k_transpose(const float* __restrict__ Wl, const float* __restrict__ Wtc) {
    int tid = blockIdx.x * 256 + threadIdx.x;
    if (blockIdx.y == 0) {
        if (tid < CIN * COUT) {
            int i = tid >> 8, o = tid & 255;
            float v = Wl[o * CIN + i];
            __half h = __float2half_rn(v);
            d_B0h[tid] = h;
            d_WTl[tid] = __float2half_rn(v - __half2float(h));
        }
    } else {
        if (tid < COUT * COUT) {
            int o = tid >> 8, e = tid & 255;
            float v = Wtc[e * COUT + o];
            d_WtcT[tid] = v;
            __half h = __float2half_rn(v);
            d_Wtch[tid] = h;
            d_Wtcl[tid] = __float2half_rn(v - __half2float(h));
        }
    }
}

// ---------------- per-batch stage 1 ----------------
__global__ __launch_bounds__(256) void k_s1(
    const float* __restrict__ ctx, const float* __restrict__ Wg,
    const float* __restrict__ bg,  const float* __restrict__ Whb,
    const float* __restrict__ Wk,  const float* __restrict__ Wv)
{
    int b = blockIdx.x;
    int tid = threadIdx.x;
    __shared__ float cs[CTXD];
    __shared__ float ks[COUT], vs[COUT], ms[COUT], invr[COUT];
    __shared__ float vmm[2];

    for (int i = tid; i < CTXD; i += 256) cs[i] = ctx[b * CTXD + i];
    __syncthreads();

    int warp = tid >> 5, lane = tid & 31;
    for (int o = warp; o < COUT; o += 8) {
        float kk = 0.f, vv = 0.f, gg = 0.f, hb = 0.f;
        for (int c = lane; c < 256; c += 32) {
            float cv = cs[c];
            kk = fmaf(cv, Wk[o * 256 + c], kk);
            vv = fmaf(cv, Wv[o * 256 + c], vv);
        }
        for (int c = lane; c < CTXD; c += 32) {
            float cv = cs[c];
            gg = fmaf(cv, Wg[o * CTXD + c], gg);
            hb = fmaf(cv, Whb[o * CTXD + c], hb);
        }
        #pragma unroll
        for (int s = 16; s; s >>= 1) {
            kk += __shfl_xor_sync(0xffffffffu, kk, s);
            vv += __shfl_xor_sync(0xffffffffu, vv, s);
            gg += __shfl_xor_sync(0xffffffffu, gg, s);
            hb += __shfl_xor_sync(0xffffffffu, hb, s);
        }
        if (lane == 0) {
            ks[o] = kk; vs[o] = vv;
            float z = gg + bg[o];
            d_gate[b * COUT + o]  = 1.f / (1.f + expf(-z));
            d_hbias[b * COUT + o] = hb;
        }
    }
    __syncthreads();

    if (tid == 0) {
        float mx = vs[0], mn = vs[0];
        for (int i = 1; i < COUT; i++) { mx = fmaxf(mx, vs[i]); mn = fminf(mn, vs[i]); }
        vmm[0] = mx; vmm[1] = mn;
    }
    __syncthreads();

    {
        float kk = ks[tid];
        float m = (kk >= 0.f) ? kk * vmm[0] : kk * vmm[1];
        float r = 0.f;
        for (int e = 0; e < COUT; e++) r += expf(fmaf(kk, vs[e], -m));
        ms[tid] = m;
        invr[tid] = 1.f / r;
    }
    __syncthreads();

    float ve = vs[tid];
    float csum = 0.f;
    for (int o = 0; o < COUT; o++)
        csum += expf(fmaf(ks[o], ve, -ms[o])) * invr[o];
    float cinv = 1.f / (1e-9f + csum);

    __half* Ahb = d_Ah + (size_t)b * (COUT * COUT);
    __half* Alb = d_Al + (size_t)b * (COUT * COUT);
    for (int o = 0; o < COUT; o++) {
        float a = expf(fmaf(ks[o], ve, -ms[o])) * invr[o] * cinv;
        __half h = __float2half_rn(a);
        Ahb[o * COUT + tid] = h;
        Alb[o * COUT + tid] = __float2half_rn(a - __half2float(h));
    }
}

// biasv: [b_layer | b_tc + (b_layer^T (I-A)) Wtc^T]
__global__ void k_bc(const float* __restrict__ b_layer, const float* __restrict__ b_tc) {
    int b = blockIdx.x, e = threadIdx.x;
    __shared__ float v[COUT];
    const __half* Ahb = d_Ah + (size_t)b * (COUT * COUT);
    const __half* Alb = d_Al + (size_t)b * (COUT * COUT);
    float s = 0.f;
    for (int o = 0; o < COUT; o++) {
        float a = __half2float(Ahb[o * COUT + e]) + __half2float(Alb[o * COUT + e]);
        s = fmaf(b_layer[o], a, s);
    }
    v[e] = b_layer[e] - s;
    __syncthreads();
    float s2 = b_tc[e];
    for (int k = 0; k < COUT; k++) s2 = fmaf(v[k], d_WtcT[k * COUT + e], s2);
    d_biasv[b * 512 + e] = b_layer[e];
    d_biasv[b * 512 + 256 + e] = s2;
}

// ---------------- BN stats ----------------
__global__ void k_bnstats2() {
    int n = blockIdx.x * 256 + threadIdx.x;
    float s = 0.f, q = 0.f;
    #pragma unroll
    for (int b = 0; b < NB; b++) {
        s += d_ps[(size_t)b * NN + n];
        q += d_pq[(size_t)b * NN + n];
    }
    float mean = s * (1.f / 8192.f);
    float var  = q * (1.f / 8192.f) - mean * mean;
    d_mean[n] = mean;
    d_rstd[n] = rsqrtf(var + 1e-5f);
}

// ---------------- launch ----------------
extern "C" void kernel_launch(void* const* d_in, const int* in_sizes, int n_in,
                              void* d_out, int out_size)
{
    (void)in_sizes; (void)n_in; (void)out_size;
    const float* ctx     = (const float*)d_in[0];
    const float* x       = (const float*)d_in[1];
    const float* W_layer = (const float*)d_in[2];
    const float* b_layer = (const float*)d_in[3];
    const float* W_hbias = (const float*)d_in[4];
    const float* W_gate  = (const float*)d_in[5];
    const float* b_gate  = (const float*)d_in[6];
    const float* W_k     = (const float*)d_in[7];
    const float* W_v     = (const float*)d_in[8];
    const float* W_tc    = (const float*)d_in[9];
    const float* b_tc    = (const float*)d_in[10];
    const float* gamma   = (const float*)d_in[11];
    const float* beta    = (const float*)d_in[12];
    float* out = (float*)d_out;

    static int smem_set = 0;
    if (!smem_set) {
        cudaFuncSetAttribute(k_gemm_half<0>,
                             cudaFuncAttributeMaxDynamicSharedMemorySize, SMEM_G_BYTES);
        cudaFuncSetAttribute(k_gemm_half<1>,
                             cudaFuncAttributeMaxDynamicSharedMemorySize, SMEM_G_BYTES);
        cudaFuncSetAttribute(k_gemm_Et,
                             cudaFuncAttributeMaxDynamicSharedMemorySize, SMEM_TS_BYTES);
        cudaFuncSetAttribute(k_gemm_D2,
                             cudaFuncAttributeMaxDynamicSharedMemorySize, SMEM_TS_BYTES);
        smem_set = 1;
    }

    k_transpose<<<dim3(256, 2), 256>>>(W_layer, W_tc);
    k_convx<<<(MTOT * CIN) / 1024, 256>>>(x);
    k_s1<<<NB, 256>>>(ctx, W_gate, b_gate, W_hbias, W_k, W_v);
    k_gemm_Et<<<dim3(2, 1, NB + 1), 256, SMEM_TS_BYTES>>>();
    k_gemm_D2<<<dim3(2, 1, NB), 256, SMEM_TS_BYTES>>>();
    k_bc<<<NB, 256>>>(b_layer, b_tc);
    k_gemm_half<0><<<512, 256, SMEM_G_BYTES>>>(b_layer, gamma, beta, out);
    k_bnstats2<<<NN / 256, 256>>>();
    k_gemm_half<1><<<512, 256, SMEM_G_BYTES>>>(b_layer, gamma, beta, out);
}